// round 2
// baseline (speedup 1.0000x reference)
#include <cuda_runtime.h>

#define BB  2
#define NN  50000
#define EE  800000
#define FF  16
#define EMBD 32
#define BNE (BB*NN*EMBD)

// ---------------- scratch (device globals; no allocation allowed) ----------------
__device__ float g_x [BNE];        // node state, layout [n][b][32]
__device__ float g_A [2*BNE];      // x@W1 (src table), double buffered
__device__ float g_Bt[2*BNE];      // x@W2 + msg_b (dst table), double buffered
__device__ int   g_deg[NN];
__device__ int   g_rowptr[NN+1];
__device__ int   g_cursor[NN];
__device__ int   g_srcp[EE];
__device__ float g_ewp [EE];
__device__ float g_gsum[BB*EMBD];
__device__ float g_h0[BB*512];
__device__ float g_d1[BB*16*8*8];
__device__ float g_d2[BB*8*16*16];
__device__ float g_d3[BB*4*32*32];
__device__ float g_d4[BB*2*64*64];
__device__ int   g_maskmode;       // 0=uint8, 1=int32, 2=float32

// ---------------- mask dtype sniffer ----------------
// Reads ONLY the first 20000 bytes (safe for u8/i32/f32 interpretations).
__global__ void k_masksniff(const unsigned int* __restrict__ m){
    __shared__ int bad_i32, bad_f32;
    if (threadIdx.x == 0){ bad_i32 = 0; bad_f32 = 0; }
    __syncthreads();
    int li = 0, lf = 0;
    for (int i = threadIdx.x; i < 5000; i += blockDim.x){
        unsigned int v = m[i];
        if (v != 0u && v != 1u) li = 1;
        if (v != 0u && v != 0x3F800000u) lf = 1;
    }
    if (li) atomicOr(&bad_i32, 1);
    if (lf) atomicOr(&bad_f32, 1);
    __syncthreads();
    if (threadIdx.x == 0){
        int mode;
        if (!bad_i32) mode = 1;       // plausible int32 {0,1}
        else if (!bad_f32) mode = 2;  // plausible float32 {0,1.0f}
        else mode = 0;                // bytes (e.g. 0x01010101 pattern)
        g_maskmode = mode;
    }
}

// ---------------- CSR build ----------------
__global__ void k_deg(const int* __restrict__ dst){
    int e = blockIdx.x*blockDim.x + threadIdx.x;
    if (e < EE) atomicAdd(&g_deg[dst[e]], 1);
}

__global__ void k_scan(){
    const int T = 1024;
    int tid = threadIdx.x, lane = tid & 31, wid = tid >> 5;
    __shared__ int wsum[32];
    __shared__ int s_carry;
    if (tid == 0) s_carry = 0;
    __syncthreads();
    for (int base = 0; base < NN; base += T){
        int i = base + tid;
        int v = (i < NN) ? g_deg[i] : 0;
        int x = v;
        #pragma unroll
        for (int off = 1; off < 32; off <<= 1){
            int t = __shfl_up_sync(0xffffffffu, x, off);
            if (lane >= off) x += t;
        }
        if (lane == 31) wsum[wid] = x;
        __syncthreads();
        if (wid == 0){
            int s = wsum[lane];
            #pragma unroll
            for (int off = 1; off < 32; off <<= 1){
                int t = __shfl_up_sync(0xffffffffu, s, off);
                if (lane >= off) s += t;
            }
            wsum[lane] = s;
        }
        __syncthreads();
        int incl = x + ((wid > 0) ? wsum[wid-1] : 0);
        int carry = s_carry;
        if (i < NN) g_rowptr[i+1] = carry + incl;
        __syncthreads();
        if (tid == T-1) s_carry = carry + incl;
        __syncthreads();
    }
    if (tid == 0) g_rowptr[0] = 0;
}

__global__ void k_scatter(const int* __restrict__ src, const int* __restrict__ dst,
                          const float* __restrict__ ew){
    int e = blockIdx.x*blockDim.x + threadIdx.x;
    if (e < EE){
        int d   = dst[e];
        int pos = g_rowptr[d] + atomicAdd(&g_cursor[d], 1);
        g_srcp[pos] = src[e];
        g_ewp [pos] = ew[e];
    }
}

// ---------------- projection + layer-0 A/Bt ----------------
__global__ __launch_bounds__(256) void k_proj(const float* __restrict__ nf,
        const float* __restrict__ pw, const float* __restrict__ pb,
        const float* __restrict__ msgw, const float* __restrict__ msgb){
    __shared__ float sP[FF*EMBD], sW1[EMBD*EMBD], sW2[EMBD*EMBD], sPB[EMBD], sMB[EMBD];
    int tid = threadIdx.x;
    for (int t = tid; t < FF*EMBD; t += 256) sP[t] = pw[t];
    for (int t = tid; t < EMBD*EMBD; t += 256){ sW1[t] = msgw[t]; sW2[t] = msgw[EMBD*EMBD + t]; }
    if (tid < EMBD){ sPB[tid] = pb[tid]; sMB[tid] = msgb[tid]; }
    __syncthreads();
    int lane = tid & 31;
    int n = blockIdx.x*8 + (tid >> 5);
    if (n >= NN) return;
    #pragma unroll
    for (int b = 0; b < BB; b++){
        float f = (lane < FF) ? nf[(b*NN + n)*FF + lane] : 0.f;
        float xv = sPB[lane];
        #pragma unroll
        for (int k = 0; k < FF; k++){
            float fk = __shfl_sync(0xffffffffu, f, k);
            xv = fmaf(fk, sP[k*EMBD + lane], xv);
        }
        int base = n*(BB*EMBD) + b*EMBD + lane;
        g_x[base] = xv;
        float av = 0.f, bv = sMB[lane];
        #pragma unroll
        for (int k = 0; k < EMBD; k++){
            float xk = __shfl_sync(0xffffffffu, xv, k);
            av = fmaf(xk, sW1[k*EMBD + lane], av);
            bv = fmaf(xk, sW2[k*EMBD + lane], bv);
        }
        g_A[base] = av; g_Bt[base] = bv;
    }
}

// ---------------- aggregation + update (+ next-layer A/Bt) ----------------
__global__ __launch_bounds__(256) void k_layer(int l,
        const float* __restrict__ msgw, const float* __restrict__ msgb,
        const float* __restrict__ updw, const float* __restrict__ updb){
    __shared__ float sU1[1024], sU2[1024], sW1[1024], sW2[1024];
    __shared__ float sUB[32], sW3[32], sMBn[32];
    int tid = threadIdx.x;
    const float* uw = updw + l*2048;
    for (int t = tid; t < 1024; t += 256){ sU1[t] = uw[t]; sU2[t] = uw[1024 + t]; }
    if (l < 2){
        const float* mw = msgw + (l+1)*2080;
        for (int t = tid; t < 1024; t += 256){ sW1[t] = mw[t]; sW2[t] = mw[1024 + t]; }
        if (tid < 32) sMBn[tid] = msgb[(l+1)*32 + tid];
    }
    if (tid < 32){ sUB[tid] = updb[l*32 + tid]; sW3[tid] = msgw[l*2080 + 2048 + tid]; }
    __syncthreads();

    int lane = tid & 31;
    int n = blockIdx.x*8 + (tid >> 5);
    if (n >= NN) return;

    int r0 = g_rowptr[n], r1 = g_rowptr[n+1];
    float inv = 1.0f / (float)max(r1 - r0, 1);
    const float* A  = g_A  + (l & 1)*BNE;
    const float* Bt = g_Bt + (l & 1)*BNE;
    int base = n*64;
    float bt0 = Bt[base + lane], bt1 = Bt[base + 32 + lane];
    float acc0 = 0.f, acc1 = 0.f;

    for (int cb = r0; cb < r1; cb += 32){
        int e = cb + lane;
        int s = 0; float w = 0.f;
        if (e < r1){ s = g_srcp[e]; w = g_ewp[e]; }
        int cnt = min(32, r1 - cb);
        for (int k = 0; k < cnt; k++){
            int   ss = __shfl_sync(0xffffffffu, s, k);
            float ww = __shfl_sync(0xffffffffu, w, k);
            float wv = ww * sW3[lane];
            float a0 = A[ss*64 + lane];
            float a1 = A[ss*64 + 32 + lane];
            acc0 += fmaxf(a0 + bt0 + wv, 0.f);
            acc1 += fmaxf(a1 + bt1 + wv, 0.f);
        }
    }
    float ag0 = acc0*inv, ag1 = acc1*inv;
    float x0 = g_x[base + lane], x1 = g_x[base + 32 + lane];
    float u0 = sUB[lane], u1 = sUB[lane];
    #pragma unroll
    for (int k = 0; k < 32; k++){
        float xk0 = __shfl_sync(0xffffffffu, x0, k);
        float xk1 = __shfl_sync(0xffffffffu, x1, k);
        float ak0 = __shfl_sync(0xffffffffu, ag0, k);
        float ak1 = __shfl_sync(0xffffffffu, ag1, k);
        float w1 = sU1[k*32 + lane], w2 = sU2[k*32 + lane];
        u0 = fmaf(xk0, w1, u0); u0 = fmaf(ak0, w2, u0);
        u1 = fmaf(xk1, w1, u1); u1 = fmaf(ak1, w2, u1);
    }
    float xn0 = fmaxf(u0, 0.f), xn1 = fmaxf(u1, 0.f);
    g_x[base + lane] = xn0; g_x[base + 32 + lane] = xn1;

    if (l < 2){
        int wsel = ((l+1) & 1)*BNE;
        float a0 = 0.f, a1 = 0.f, b0 = sMBn[lane], b1 = sMBn[lane];
        #pragma unroll
        for (int k = 0; k < 32; k++){
            float xk0 = __shfl_sync(0xffffffffu, xn0, k);
            float xk1 = __shfl_sync(0xffffffffu, xn1, k);
            float w1 = sW1[k*32 + lane], w2 = sW2[k*32 + lane];
            a0 = fmaf(xk0, w1, a0); b0 = fmaf(xk0, w2, b0);
            a1 = fmaf(xk1, w1, a1); b1 = fmaf(xk1, w2, b1);
        }
        g_A [wsel + base + lane] = a0; g_A [wsel + base + 32 + lane] = a1;
        g_Bt[wsel + base + lane] = b0; g_Bt[wsel + base + 32 + lane] = b1;
    }
}

// ---------------- graph mean ----------------
__global__ void k_mean(){
    int lane = threadIdx.x & 31, warp = threadIdx.x >> 5;
    int gw = blockIdx.x*8 + warp;
    int nwarp = gridDim.x*8;
    float acc0 = 0.f, acc1 = 0.f;
    for (int n = gw; n < NN; n += nwarp){
        acc0 += g_x[n*64 + lane];
        acc1 += g_x[n*64 + 32 + lane];
    }
    __shared__ float s0[8][32], s1[8][32];
    s0[warp][lane] = acc0; s1[warp][lane] = acc1;
    __syncthreads();
    if (warp == 0){
        float t0 = 0.f, t1 = 0.f;
        #pragma unroll
        for (int i = 0; i < 8; i++){ t0 += s0[i][lane]; t1 += s1[i][lane]; }
        atomicAdd(&g_gsum[lane], t0);
        atomicAdd(&g_gsum[32 + lane], t1);
    }
}

// ---------------- head: combined + policy + value ----------------
__global__ __launch_bounds__(512) void k_head(const int* __restrict__ macro_idx,
        const float* __restrict__ meta,
        const float* __restrict__ mw, const float* __restrict__ mb,
        const float* __restrict__ metw, const float* __restrict__ metb,
        const float* __restrict__ pw, const float* __restrict__ pb,
        const float* __restrict__ vw1, const float* __restrict__ vb1,
        const float* __restrict__ vw2, const float* __restrict__ vb2,
        float* __restrict__ out, int out_total){
    __shared__ float comb[2*80];
    __shared__ float v1[2*32];
    int tid = threadIdx.x;
    if (tid < 64){
        int b = tid >> 5, j = tid & 31;
        comb[b*80 + j] = g_gsum[b*32 + j] * (1.0f/NN);
    } else if (tid < 128){
        int t = tid - 64, b = t >> 5, j = t & 31;
        int mi = macro_idx[b];
        const float* xr = g_x + mi*64 + b*32;
        float acc = mb[j];
        for (int k = 0; k < 32; k++) acc = fmaf(xr[k], mw[k*32 + j], acc);
        comb[b*80 + 32 + j] = acc;
    } else if (tid < 160){
        int t = tid - 128, b = t >> 4, j = t & 15;
        float acc = metb[j];
        for (int k = 0; k < 4; k++) acc = fmaf(meta[b*4 + k], metw[k*16 + j], acc);
        comb[b*80 + 64 + j] = fmaxf(acc, 0.f);
    }
    __syncthreads();
    for (int b = 0; b < 2; b++){
        float acc = pb[tid];
        for (int k = 0; k < 80; k++) acc = fmaf(comb[b*80 + k], pw[k*512 + tid], acc);
        g_h0[b*512 + tid] = fmaxf(acc, 0.f);
    }
    if (tid < 64){
        int b = tid >> 5, j = tid & 31;
        float acc = vb1[j];
        for (int k = 0; k < 80; k++) acc = fmaf(comb[b*80 + k], vw1[k*32 + j], acc);
        v1[b*32 + j] = fmaxf(acc, 0.f);
    }
    __syncthreads();
    if (tid < 2){
        float acc = vb2[0];
        for (int k = 0; k < 32; k++) acc = fmaf(v1[tid*32 + k], vw2[k], acc);
        out[20000 + tid] = acc;
    }
}

// ---------------- deconvs ----------------
__global__ void k_deconv(const float* __restrict__ in, const float* __restrict__ w,
                         const float* __restrict__ bias, float* __restrict__ out,
                         int Cin, int Cout, int Hin, int do_relu){
    int Hout = Hin*2;
    int total = BB*Cout*Hout*Hout;
    int idx = blockIdx.x*blockDim.x + threadIdx.x;
    if (idx >= total) return;
    int x = idx % Hout;
    int y = (idx/Hout) % Hout;
    int o = (idx/(Hout*Hout)) % Cout;
    int b = idx/(Hout*Hout*Cout);
    float acc = bias[o];
    for (int kh = 0; kh < 4; kh++){
        int ty = y + 1 - kh; if (ty < 0 || (ty & 1)) continue;
        int p = ty >> 1; if (p >= Hin) continue;
        for (int kw = 0; kw < 4; kw++){
            int tx = x + 1 - kw; if (tx < 0 || (tx & 1)) continue;
            int q = tx >> 1; if (q >= Hin) continue;
            for (int i = 0; i < Cin; i++)
                acc = fmaf(in[((b*Cin + i)*Hin + p)*Hin + q],
                           w[((i*Cout + o)*4 + kh)*4 + kw], acc);
        }
    }
    out[idx] = do_relu ? fmaxf(acc, 0.f) : acc;
}

__global__ void k_final(const float* __restrict__ w, const float* __restrict__ bias,
                        const void* __restrict__ maskp, float* __restrict__ out){
    int idx = blockIdx.x*blockDim.x + threadIdx.x;
    if (idx >= BB*100*100) return;
    int x = idx % 100;
    int y = (idx/100) % 100;
    int b = idx/10000;
    float acc = bias[0];
    const float* in = g_d4 + b*2*64*64;
    for (int kh = 0; kh < 4; kh++){
        int ty = y + 1 - kh; if (ty < 0 || (ty & 1)) continue;
        int p = ty >> 1; if (p >= 64) continue;
        for (int kw = 0; kw < 4; kw++){
            int tx = x + 1 - kw; if (tx < 0 || (tx & 1)) continue;
            int q = tx >> 1; if (q >= 64) continue;
            acc = fmaf(in[p*64 + q],        w[kh*4 + kw],      acc);
            acc = fmaf(in[4096 + p*64 + q], w[16 + kh*4 + kw], acc);
        }
    }
    int mode = g_maskmode;
    bool mv;
    if (mode == 1)      mv = ((const int*)maskp)[idx] != 0;
    else if (mode == 2) mv = ((const float*)maskp)[idx] != 0.0f;
    else                mv = ((const unsigned char*)maskp)[idx] != 0;
    out[idx] = mv ? acc : -100000000.0f;
}

// ---------------- launch ----------------
extern "C" void kernel_launch(void* const* d_in, const int* in_sizes, int n_in,
                              void* d_out, int out_size){
    const float* nf   = (const float*)d_in[0];
    const int*   ei   = (const int*)  d_in[1];
    const float* ew   = (const float*)d_in[2];
    const int*   midx = (const int*)  d_in[3];
    const float* meta = (const float*)d_in[4];
    const void*  mask = (const void*) d_in[5];
    const float* pw   = (const float*)d_in[6];
    const float* pbb  = (const float*)d_in[7];
    const float* msgw = (const float*)d_in[8];
    const float* msgb = (const float*)d_in[9];
    const float* updw = (const float*)d_in[10];
    const float* updb = (const float*)d_in[11];
    const float* macw = (const float*)d_in[12];
    const float* macb = (const float*)d_in[13];
    const float* metw = (const float*)d_in[14];
    const float* metb = (const float*)d_in[15];
    const float* polw = (const float*)d_in[16];
    const float* polb = (const float*)d_in[17];
    const float* dcw1 = (const float*)d_in[18];
    const float* dcb1 = (const float*)d_in[19];
    const float* dcw2 = (const float*)d_in[20];
    const float* dcb2 = (const float*)d_in[21];
    const float* dcw3 = (const float*)d_in[22];
    const float* dcb3 = (const float*)d_in[23];
    const float* dcw4 = (const float*)d_in[24];
    const float* dcb4 = (const float*)d_in[25];
    const float* dcw5 = (const float*)d_in[26];
    const float* dcb5 = (const float*)d_in[27];
    const float* vw1  = (const float*)d_in[28];
    const float* vb1  = (const float*)d_in[29];
    const float* vw2  = (const float*)d_in[30];
    const float* vb2  = (const float*)d_in[31];
    float* out = (float*)d_out;

    void* p;
    cudaGetSymbolAddress(&p, g_deg);    cudaMemsetAsync(p, 0, NN*sizeof(int));
    cudaGetSymbolAddress(&p, g_cursor); cudaMemsetAsync(p, 0, NN*sizeof(int));
    cudaGetSymbolAddress(&p, g_gsum);   cudaMemsetAsync(p, 0, BB*EMBD*sizeof(float));

    const int* src = ei;
    const int* dst = ei + EE;

    k_masksniff<<<1, 256>>>((const unsigned int*)mask);
    k_deg    <<<(EE+255)/256, 256>>>(dst);
    k_scan   <<<1, 1024>>>();
    k_scatter<<<(EE+255)/256, 256>>>(src, dst, ew);
    k_proj   <<<(NN+7)/8, 256>>>(nf, pw, pbb, msgw, msgb);
    for (int l = 0; l < 3; l++)
        k_layer<<<(NN+7)/8, 256>>>(l, msgw, msgb, updw, updb);
    k_mean<<<256, 256>>>();
    k_head<<<1, 512>>>(midx, meta, macw, macb, metw, metb, polw, polb,
                       vw1, vb1, vw2, vb2, out, out_size);

    void *ph, *p1, *p2, *p3, *p4;
    cudaGetSymbolAddress(&ph, g_h0);
    cudaGetSymbolAddress(&p1, g_d1);
    cudaGetSymbolAddress(&p2, g_d2);
    cudaGetSymbolAddress(&p3, g_d3);
    cudaGetSymbolAddress(&p4, g_d4);
    k_deconv<<<(2*16*8*8   + 127)/128, 128>>>((float*)ph, dcw1, dcb1, (float*)p1, 32, 16, 4, 1);
    k_deconv<<<(2*8*16*16  + 127)/128, 128>>>((float*)p1, dcw2, dcb2, (float*)p2, 16, 8, 8, 1);
    k_deconv<<<(2*4*32*32  + 127)/128, 128>>>((float*)p2, dcw3, dcb3, (float*)p3, 8, 4, 16, 1);
    k_deconv<<<(2*2*64*64  + 127)/128, 128>>>((float*)p3, dcw4, dcb4, (float*)p4, 4, 2, 32, 1);
    k_final <<<(20000      + 127)/128, 128>>>(dcw5, dcb5, mask, out);
}

// round 6
// speedup vs baseline: 1.0409x; 1.0409x over previous
#include <cuda_runtime.h>

#define BB  2
#define NN  50000
#define EE  800000
#define FF  16
#define EMBD 32
#define BNE (BB*NN*EMBD)

// ---------------- scratch ----------------
__device__ float g_x [BNE];
__device__ float g_A [2*BNE];
__device__ float g_Bt[2*BNE];
__device__ int   g_deg[NN];
__device__ int   g_rowptr[NN+1];
__device__ int   g_cursor[NN];
__device__ int   g_srcp[EE];
__device__ float g_ewp [EE];
__device__ float g_gsum[BB*EMBD];
__device__ int   g_bsum[64];
__device__ float g_d4[BB*2*64*64];
__device__ int   g_maskmode;

// ---------------- mask dtype sniffer ----------------
__global__ void k_masksniff(const unsigned int* __restrict__ m){
    __shared__ int bad_i32, bad_f32;
    if (threadIdx.x == 0){ bad_i32 = 0; bad_f32 = 0; }
    __syncthreads();
    int li = 0, lf = 0;
    for (int i = threadIdx.x; i < 5000; i += blockDim.x){
        unsigned int v = m[i];
        if (v != 0u && v != 1u) li = 1;
        if (v != 0u && v != 0x3F800000u) lf = 1;
    }
    if (li) atomicOr(&bad_i32, 1);
    if (lf) atomicOr(&bad_f32, 1);
    __syncthreads();
    if (threadIdx.x == 0){
        int mode;
        if (!bad_i32) mode = 1;
        else if (!bad_f32) mode = 2;
        else mode = 0;
        g_maskmode = mode;
    }
}

// ---------------- CSR build ----------------
__global__ void k_deg(const int* __restrict__ dst){
    int e = blockIdx.x*blockDim.x + threadIdx.x;
    if (e < EE) atomicAdd(&g_deg[dst[e]], 1);
}

// parallel scan: 49 blocks x 1024
__global__ __launch_bounds__(1024) void k_scan1(){
    int tid = threadIdx.x, lane = tid & 31, wid = tid >> 5;
    int i = blockIdx.x*1024 + tid;
    int v = (i < NN) ? g_deg[i] : 0;
    int x = v;
    #pragma unroll
    for (int off = 1; off < 32; off <<= 1){
        int t = __shfl_up_sync(0xffffffffu, x, off);
        if (lane >= off) x += t;
    }
    __shared__ int ws[32];
    if (lane == 31) ws[wid] = x;
    __syncthreads();
    if (wid == 0){
        int s = ws[lane];
        #pragma unroll
        for (int off = 1; off < 32; off <<= 1){
            int t = __shfl_up_sync(0xffffffffu, s, off);
            if (lane >= off) s += t;
        }
        ws[lane] = s;
    }
    __syncthreads();
    int incl = x + (wid ? ws[wid-1] : 0);
    if (i < NN) g_rowptr[i+1] = incl;
    if (tid == 1023) g_bsum[blockIdx.x] = incl;
}

__global__ void k_scan2(){
    int tid = threadIdx.x, lane = tid & 31, wid = tid >> 5;  // 64 threads
    int v = (tid < 49) ? g_bsum[tid] : 0;
    int x = v;
    #pragma unroll
    for (int off = 1; off < 32; off <<= 1){
        int t = __shfl_up_sync(0xffffffffu, x, off);
        if (lane >= off) x += t;
    }
    __shared__ int w2[2];
    if (lane == 31) w2[wid] = x;
    __syncthreads();
    int incl = x + (wid ? w2[0] : 0);
    if (tid < 49) g_bsum[tid] = incl - v;   // exclusive
}

__global__ __launch_bounds__(1024) void k_scan3(){
    int i = blockIdx.x*1024 + threadIdx.x;
    int off = g_bsum[blockIdx.x];
    if (i < NN) g_rowptr[i+1] += off;
    if (i == 0) g_rowptr[0] = 0;
}

__global__ void k_scatter(const int* __restrict__ src, const int* __restrict__ dst,
                          const float* __restrict__ ew){
    int e = blockIdx.x*blockDim.x + threadIdx.x;
    if (e < EE){
        int d   = dst[e];
        int pos = g_rowptr[d] + atomicAdd(&g_cursor[d], 1);
        g_srcp[pos] = src[e];
        g_ewp [pos] = ew[e];
    }
}

// ---------------- projection + layer-0 A/Bt ----------------
__global__ __launch_bounds__(256) void k_proj(const float* __restrict__ nf,
        const float* __restrict__ pw, const float* __restrict__ pb,
        const float* __restrict__ msgw, const float* __restrict__ msgb){
    __shared__ float sP[FF*EMBD], sW1[EMBD*EMBD], sW2[EMBD*EMBD], sPB[EMBD], sMB[EMBD];
    int tid = threadIdx.x;
    for (int t = tid; t < FF*EMBD; t += 256) sP[t] = pw[t];
    for (int t = tid; t < EMBD*EMBD; t += 256){ sW1[t] = msgw[t]; sW2[t] = msgw[EMBD*EMBD + t]; }
    if (tid < EMBD){ sPB[tid] = pb[tid]; sMB[tid] = msgb[tid]; }
    __syncthreads();
    int lane = tid & 31;
    int n = blockIdx.x*8 + (tid >> 5);
    if (n >= NN) return;
    #pragma unroll
    for (int b = 0; b < BB; b++){
        float f = (lane < FF) ? nf[(b*NN + n)*FF + lane] : 0.f;
        float xv = sPB[lane];
        #pragma unroll
        for (int k = 0; k < FF; k++){
            float fk = __shfl_sync(0xffffffffu, f, k);
            xv = fmaf(fk, sP[k*EMBD + lane], xv);
        }
        int base = n*(BB*EMBD) + b*EMBD + lane;
        g_x[base] = xv;
        float av = 0.f, bv = sMB[lane];
        #pragma unroll
        for (int k = 0; k < EMBD; k++){
            float xk = __shfl_sync(0xffffffffu, xv, k);
            av = fmaf(xk, sW1[k*EMBD + lane], av);
            bv = fmaf(xk, sW2[k*EMBD + lane], bv);
        }
        g_A[base] = av; g_Bt[base] = bv;
    }
}

// ---------------- aggregation + update (+ next-layer A/Bt) ----------------
__global__ __launch_bounds__(256) void k_layer(int l,
        const float* __restrict__ msgw, const float* __restrict__ msgb,
        const float* __restrict__ updw, const float* __restrict__ updb){
    __shared__ float sU1[1024], sU2[1024], sW1[1024], sW2[1024];
    __shared__ float sUB[32], sW3[32], sMBn[32];
    int tid = threadIdx.x;
    const float* uw = updw + l*2048;
    for (int t = tid; t < 1024; t += 256){ sU1[t] = uw[t]; sU2[t] = uw[1024 + t]; }
    if (l < 2){
        const float* mw = msgw + (l+1)*2080;
        for (int t = tid; t < 1024; t += 256){ sW1[t] = mw[t]; sW2[t] = mw[1024 + t]; }
        if (tid < 32) sMBn[tid] = msgb[(l+1)*32 + tid];
    }
    if (tid < 32){ sUB[tid] = updb[l*32 + tid]; sW3[tid] = msgw[l*2080 + 2048 + tid]; }
    __syncthreads();

    int lane = tid & 31;
    int n = blockIdx.x*8 + (tid >> 5);
    if (n >= NN) return;

    int r0 = g_rowptr[n], r1 = g_rowptr[n+1];
    float inv = 1.0f / (float)max(r1 - r0, 1);
    const float* __restrict__ A  = g_A  + (l & 1)*BNE;
    const float* __restrict__ Bt = g_Bt + (l & 1)*BNE;
    int base = n*64;
    float w3l = sW3[lane];
    float bt0 = Bt[base + lane], bt1 = Bt[base + 32 + lane];
    float acc0 = 0.f, acc1 = 0.f;

    for (int cb = r0; cb < r1; cb += 32){
        int e = cb + lane;
        int s = 0; float w = 0.f;
        if (e < r1){ s = g_srcp[e]; w = g_ewp[e]; }
        int cnt = min(32, r1 - cb);
        int kk = 0;
        // unrolled-by-8: 16 independent loads in flight
        for (; kk + 8 <= cnt; kk += 8){
            float a0[8], a1[8], wv[8];
            #pragma unroll
            for (int j = 0; j < 8; j++){
                int ss   = __shfl_sync(0xffffffffu, s, kk + j);
                wv[j]    = __shfl_sync(0xffffffffu, w, kk + j);
                const float* ap = A + ss*64 + lane;
                a0[j] = ap[0];
                a1[j] = ap[32];
            }
            #pragma unroll
            for (int j = 0; j < 8; j++){
                float t = wv[j]*w3l;
                acc0 += fmaxf(a0[j] + bt0 + t, 0.f);
                acc1 += fmaxf(a1[j] + bt1 + t, 0.f);
            }
        }
        for (; kk < cnt; kk++){
            int   ss = __shfl_sync(0xffffffffu, s, kk);
            float ww = __shfl_sync(0xffffffffu, w, kk);
            float t = ww*w3l;
            acc0 += fmaxf(A[ss*64 + lane]      + bt0 + t, 0.f);
            acc1 += fmaxf(A[ss*64 + 32 + lane] + bt1 + t, 0.f);
        }
    }
    float ag0 = acc0*inv, ag1 = acc1*inv;
    float x0 = g_x[base + lane], x1 = g_x[base + 32 + lane];
    float u0 = sUB[lane], u1 = sUB[lane];
    #pragma unroll
    for (int k = 0; k < 32; k++){
        float xk0 = __shfl_sync(0xffffffffu, x0, k);
        float xk1 = __shfl_sync(0xffffffffu, x1, k);
        float ak0 = __shfl_sync(0xffffffffu, ag0, k);
        float ak1 = __shfl_sync(0xffffffffu, ag1, k);
        float w1 = sU1[k*32 + lane], w2 = sU2[k*32 + lane];
        u0 = fmaf(xk0, w1, u0); u0 = fmaf(ak0, w2, u0);
        u1 = fmaf(xk1, w1, u1); u1 = fmaf(ak1, w2, u1);
    }
    float xn0 = fmaxf(u0, 0.f), xn1 = fmaxf(u1, 0.f);
    g_x[base + lane] = xn0; g_x[base + 32 + lane] = xn1;

    if (l < 2){
        int wsel = ((l+1) & 1)*BNE;
        float a0 = 0.f, a1 = 0.f, b0 = sMBn[lane], b1 = sMBn[lane];
        #pragma unroll
        for (int k = 0; k < 32; k++){
            float xk0 = __shfl_sync(0xffffffffu, xn0, k);
            float xk1 = __shfl_sync(0xffffffffu, xn1, k);
            float w1 = sW1[k*32 + lane], w2 = sW2[k*32 + lane];
            a0 = fmaf(xk0, w1, a0); b0 = fmaf(xk0, w2, b0);
            a1 = fmaf(xk1, w1, a1); b1 = fmaf(xk1, w2, b1);
        }
        g_A [wsel + base + lane] = a0; g_A [wsel + base + 32 + lane] = a1;
        g_Bt[wsel + base + lane] = b0; g_Bt[wsel + base + 32 + lane] = b1;
    }
}

// ---------------- graph mean ----------------
__global__ void k_mean(){
    int lane = threadIdx.x & 31, warp = threadIdx.x >> 5;
    int gw = blockIdx.x*8 + warp;
    int nwarp = gridDim.x*8;
    float acc0 = 0.f, acc1 = 0.f;
    for (int n = gw; n < NN; n += nwarp){
        acc0 += g_x[n*64 + lane];
        acc1 += g_x[n*64 + 32 + lane];
    }
    __shared__ float s0[8][32], s1[8][32];
    s0[warp][lane] = acc0; s1[warp][lane] = acc1;
    __syncthreads();
    if (warp == 0){
        float t0 = 0.f, t1 = 0.f;
        #pragma unroll
        for (int i = 0; i < 8; i++){ t0 += s0[i][lane]; t1 += s1[i][lane]; }
        atomicAdd(&g_gsum[lane], t0);
        atomicAdd(&g_gsum[32 + lane], t1);
    }
}

// ---------------- fused tail: head + value + 5 deconvs + mask ----------------
__device__ __forceinline__ void deconv_sm(const float* __restrict__ in,
        const float* __restrict__ w, const float* __restrict__ bias,
        float* __restrict__ outp, int Cin, int Cout, int Hin, int tid){
    int Hout = Hin*2, total = Cout*Hout*Hout;
    for (int idx = tid; idx < total; idx += 1024){
        int x = idx % Hout;
        int y = (idx/Hout) % Hout;
        int o = idx/(Hout*Hout);
        float acc = bias[o];
        #pragma unroll
        for (int kh = 0; kh < 4; kh++){
            int ty = y + 1 - kh; if (ty < 0 || (ty & 1)) continue;
            int p = ty >> 1; if (p >= Hin) continue;
            #pragma unroll
            for (int kw = 0; kw < 4; kw++){
                int tx = x + 1 - kw; if (tx < 0 || (tx & 1)) continue;
                int q = tx >> 1; if (q >= Hin) continue;
                for (int i = 0; i < Cin; i++)
                    acc = fmaf(in[(i*Hin + p)*Hin + q],
                               w[((i*Cout + o)*4 + kh)*4 + kw], acc);
            }
        }
        outp[idx] = fmaxf(acc, 0.f);
    }
}

__global__ __launch_bounds__(1024) void k_tail(const int* __restrict__ macro_idx,
        const float* __restrict__ meta,
        const float* __restrict__ mw, const float* __restrict__ mb,
        const float* __restrict__ metw, const float* __restrict__ metb,
        const float* __restrict__ pw, const float* __restrict__ pb,
        const float* __restrict__ dcw1, const float* __restrict__ dcb1,
        const float* __restrict__ dcw2, const float* __restrict__ dcb2,
        const float* __restrict__ dcw3, const float* __restrict__ dcb3,
        const float* __restrict__ dcw4, const float* __restrict__ dcb4,
        const float* __restrict__ dcw5, const float* __restrict__ dcb5,
        const float* __restrict__ vw1, const float* __restrict__ vb1,
        const float* __restrict__ vw2, const float* __restrict__ vb2,
        const void* __restrict__ maskp, float* __restrict__ out){
    __shared__ float comb[80], v1s[32], h0s[512];
    __shared__ float bufA[4096], bufB[2048];
    int b = blockIdx.x;
    int tid = threadIdx.x;

    if (tid < 32){
        comb[tid] = g_gsum[b*32 + tid] * (1.0f/NN);
    } else if (tid < 64){
        int j = tid - 32;
        int mi = macro_idx[b];
        const float* xr = g_x + mi*64 + b*32;
        float acc = mb[j];
        for (int k = 0; k < 32; k++) acc = fmaf(xr[k], mw[k*32 + j], acc);
        comb[32 + j] = acc;
    } else if (tid < 80){
        int j = tid - 64;
        float acc = metb[j];
        for (int k = 0; k < 4; k++) acc = fmaf(meta[b*4 + k], metw[k*16 + j], acc);
        comb[64 + j] = fmaxf(acc, 0.f);
    }
    __syncthreads();

    if (tid < 512){
        float acc = pb[tid];
        for (int k = 0; k < 80; k++) acc = fmaf(comb[k], pw[k*512 + tid], acc);
        h0s[tid] = fmaxf(acc, 0.f);
    } else if (tid < 544){
        int j = tid - 512;
        float acc = vb1[j];
        for (int k = 0; k < 80; k++) acc = fmaf(comb[k], vw1[k*32 + j], acc);
        v1s[j] = fmaxf(acc, 0.f);
    }
    __syncthreads();
    if (tid == 544){
        float acc = vb2[0];
        for (int k = 0; k < 32; k++) acc = fmaf(v1s[k], vw2[k], acc);
        out[20000 + b] = acc;
    }

    deconv_sm(h0s,  dcw1, dcb1, bufA, 32, 16,  4, tid); __syncthreads();   // 16x8x8
    deconv_sm(bufA, dcw2, dcb2, bufB, 16,  8,  8, tid); __syncthreads();   // 8x16x16
    deconv_sm(bufB, dcw3, dcb3, bufA,  8,  4, 16, tid); __syncthreads();   // 4x32x32
    float* d4 = g_d4 + b*8192;
    deconv_sm(bufA, dcw4, dcb4, d4,    4,  2, 32, tid); __syncthreads();   // 2x64x64

    int mode = g_maskmode;
    for (int idx = tid; idx < 10000; idx += 1024){
        int x = idx % 100, y = idx / 100;
        float acc = dcb5[0];
        #pragma unroll
        for (int kh = 0; kh < 4; kh++){
            int ty = y + 1 - kh; if (ty < 0 || (ty & 1)) continue;
            int p = ty >> 1; if (p >= 64) continue;
            #pragma unroll
            for (int kw = 0; kw < 4; kw++){
                int tx = x + 1 - kw; if (tx < 0 || (tx & 1)) continue;
                int q = tx >> 1; if (q >= 64) continue;
                acc = fmaf(d4[p*64 + q],        dcw5[kh*4 + kw],      acc);
                acc = fmaf(d4[4096 + p*64 + q], dcw5[16 + kh*4 + kw], acc);
            }
        }
        int gidx = b*10000 + idx;
        bool mv;
        if (mode == 1)      mv = ((const int*)maskp)[gidx] != 0;
        else if (mode == 2) mv = ((const float*)maskp)[gidx] != 0.0f;
        else                mv = ((const unsigned char*)maskp)[gidx] != 0;
        out[gidx] = mv ? acc : -100000000.0f;
    }
}

// ---------------- launch ----------------
extern "C" void kernel_launch(void* const* d_in, const int* in_sizes, int n_in,
                              void* d_out, int out_size){
    const float* nf   = (const float*)d_in[0];
    const int*   ei   = (const int*)  d_in[1];
    const float* ew   = (const float*)d_in[2];
    const int*   midx = (const int*)  d_in[3];
    const float* meta = (const float*)d_in[4];
    const void*  mask = (const void*) d_in[5];
    const float* pw   = (const float*)d_in[6];
    const float* pbb  = (const float*)d_in[7];
    const float* msgw = (const float*)d_in[8];
    const float* msgb = (const float*)d_in[9];
    const float* updw = (const float*)d_in[10];
    const float* updb = (const float*)d_in[11];
    const float* macw = (const float*)d_in[12];
    const float* macb = (const float*)d_in[13];
    const float* metw = (const float*)d_in[14];
    const float* metb = (const float*)d_in[15];
    const float* polw = (const float*)d_in[16];
    const float* polb = (const float*)d_in[17];
    const float* dcw1 = (const float*)d_in[18];
    const float* dcb1 = (const float*)d_in[19];
    const float* dcw2 = (const float*)d_in[20];
    const float* dcb2 = (const float*)d_in[21];
    const float* dcw3 = (const float*)d_in[22];
    const float* dcb3 = (const float*)d_in[23];
    const float* dcw4 = (const float*)d_in[24];
    const float* dcb4 = (const float*)d_in[25];
    const float* dcw5 = (const float*)d_in[26];
    const float* dcb5 = (const float*)d_in[27];
    const float* vw1  = (const float*)d_in[28];
    const float* vb1  = (const float*)d_in[29];
    const float* vw2  = (const float*)d_in[30];
    const float* vb2  = (const float*)d_in[31];
    float* out = (float*)d_out;

    void* p;
    cudaGetSymbolAddress(&p, g_deg);    cudaMemsetAsync(p, 0, NN*sizeof(int));
    cudaGetSymbolAddress(&p, g_cursor); cudaMemsetAsync(p, 0, NN*sizeof(int));
    cudaGetSymbolAddress(&p, g_gsum);   cudaMemsetAsync(p, 0, BB*EMBD*sizeof(float));

    const int* src = ei;
    const int* dst = ei + EE;

    k_masksniff<<<1, 256>>>((const unsigned int*)mask);
    k_deg    <<<(EE+255)/256, 256>>>(dst);
    k_scan1  <<<49, 1024>>>();
    k_scan2  <<<1, 64>>>();
    k_scan3  <<<49, 1024>>>();
    k_scatter<<<(EE+255)/256, 256>>>(src, dst, ew);
    k_proj   <<<(NN+7)/8, 256>>>(nf, pw, pbb, msgw, msgb);
    for (int l = 0; l < 3; l++)
        k_layer<<<(NN+7)/8, 256>>>(l, msgw, msgb, updw, updb);
    k_mean<<<256, 256>>>();
    k_tail<<<2, 1024>>>(midx, meta, macw, macb, metw, metb, polw, polb,
                        dcw1, dcb1, dcw2, dcb2, dcw3, dcb3, dcw4, dcb4, dcw5, dcb5,
                        vw1, vb1, vw2, vb2, mask, out);
}